// round 2
// baseline (speedup 1.0000x reference)
#include <cuda_runtime.h>

#define B_ROWS 8192
#define D_IN   768
#define D_LAT  12288
#define K_TOP  64

// Scratch (device globals: no runtime allocation allowed)
__device__ float g_H[(size_t)B_ROWS * D_LAT];      // 402 MB pre-activation
__device__ float g_topv[B_ROWS * K_TOP];
__device__ int   g_topi[B_ROWS * K_TOP];

// ---------------------------------------------------------------------------
// Kernel 1: H = X @ W_enc + b_enc   (fp32 SIMT GEMM, 128x128x16, 8x8/thread)
// ---------------------------------------------------------------------------
#define BM 128
#define BN 128
#define BK 16

__global__ __launch_bounds__(256, 2)
void gemm_enc_kernel(const float* __restrict__ X, const float* __restrict__ W,
                     const float* __restrict__ bias)
{
    __shared__ float As[2][BK][BM];
    __shared__ float Bs[2][BK][BN];

    const int tid  = threadIdx.x;
    const int tx   = tid & 15;
    const int ty   = tid >> 4;
    const int row0 = blockIdx.y * BM;
    const int col0 = blockIdx.x * BN;

    const float4* X4 = reinterpret_cast<const float4*>(X);
    const float4* W4 = reinterpret_cast<const float4*>(W);

    // A load mapping: 512 float4 per tile, 2 per thread
    const int a_m  = tid >> 2;    // 0..63, +64 for second
    const int a_k4 = tid & 3;     // float4 index inside BK
    // B load mapping
    const int b_k  = tid >> 5;    // 0..7, +8 for second
    const int b_n4 = tid & 31;

    float4 aReg[2], bReg[2];
    float acc[8][8];
    #pragma unroll
    for (int i = 0; i < 8; i++)
        #pragma unroll
        for (int j = 0; j < 8; j++) acc[i][j] = 0.f;

    const int KT = D_IN / BK;  // 48

    // prologue: tile 0
    {
        #pragma unroll
        for (int i = 0; i < 2; i++) {
            int m = a_m + i * 64;
            aReg[i] = X4[(size_t)(row0 + m) * (D_IN / 4) + a_k4];
            int k = b_k + i * 8;
            bReg[i] = W4[(size_t)k * (D_LAT / 4) + (col0 >> 2) + b_n4];
        }
        #pragma unroll
        for (int i = 0; i < 2; i++) {
            int m = a_m + i * 64;
            As[0][a_k4 * 4 + 0][m] = aReg[i].x;
            As[0][a_k4 * 4 + 1][m] = aReg[i].y;
            As[0][a_k4 * 4 + 2][m] = aReg[i].z;
            As[0][a_k4 * 4 + 3][m] = aReg[i].w;
            int k = b_k + i * 8;
            *reinterpret_cast<float4*>(&Bs[0][k][b_n4 * 4]) = bReg[i];
        }
    }
    __syncthreads();

    int buf = 0;
    for (int kt = 0; kt < KT; kt++) {
        if (kt + 1 < KT) {
            #pragma unroll
            for (int i = 0; i < 2; i++) {
                int m = a_m + i * 64;
                aReg[i] = X4[(size_t)(row0 + m) * (D_IN / 4) + (kt + 1) * (BK / 4) + a_k4];
                int k = b_k + i * 8;
                bReg[i] = W4[(size_t)((kt + 1) * BK + k) * (D_LAT / 4) + (col0 >> 2) + b_n4];
            }
        }
        #pragma unroll
        for (int k = 0; k < BK; k++) {
            float a[8], b[8];
            *reinterpret_cast<float4*>(&a[0]) = *reinterpret_cast<const float4*>(&As[buf][k][ty * 8]);
            *reinterpret_cast<float4*>(&a[4]) = *reinterpret_cast<const float4*>(&As[buf][k][ty * 8 + 4]);
            *reinterpret_cast<float4*>(&b[0]) = *reinterpret_cast<const float4*>(&Bs[buf][k][tx * 8]);
            *reinterpret_cast<float4*>(&b[4]) = *reinterpret_cast<const float4*>(&Bs[buf][k][tx * 8 + 4]);
            #pragma unroll
            for (int i = 0; i < 8; i++)
                #pragma unroll
                for (int j = 0; j < 8; j++)
                    acc[i][j] = fmaf(a[i], b[j], acc[i][j]);
        }
        if (kt + 1 < KT) {
            int nb = buf ^ 1;
            #pragma unroll
            for (int i = 0; i < 2; i++) {
                int m = a_m + i * 64;
                As[nb][a_k4 * 4 + 0][m] = aReg[i].x;
                As[nb][a_k4 * 4 + 1][m] = aReg[i].y;
                As[nb][a_k4 * 4 + 2][m] = aReg[i].z;
                As[nb][a_k4 * 4 + 3][m] = aReg[i].w;
                int k = b_k + i * 8;
                *reinterpret_cast<float4*>(&Bs[nb][k][b_n4 * 4]) = bReg[i];
            }
        }
        __syncthreads();
        buf ^= 1;
    }

    // epilogue: add bias, store
    float bb[8];
    #pragma unroll
    for (int j = 0; j < 8; j++) bb[j] = bias[col0 + tx * 8 + j];
    #pragma unroll
    for (int i = 0; i < 8; i++) {
        int row = row0 + ty * 8 + i;
        float4 v0 = make_float4(acc[i][0] + bb[0], acc[i][1] + bb[1],
                                acc[i][2] + bb[2], acc[i][3] + bb[3]);
        float4 v1 = make_float4(acc[i][4] + bb[4], acc[i][5] + bb[5],
                                acc[i][6] + bb[6], acc[i][7] + bb[7]);
        float4* H4 = reinterpret_cast<float4*>(g_H + (size_t)row * D_LAT + col0 + tx * 8);
        H4[0] = v0;
        H4[1] = v1;
    }
}

// ---------------------------------------------------------------------------
// Kernel 2: per-row exact top-64 via 4-pass radix select.
// Reads the row from global each pass (row = 48 KB -> L1-resident after pass
// 1, so passes 2..5 are L1 hits). No dynamic smem => no 48 KB limit issues.
// Writes selected values into z (rest already zeroed) + compact (idx,val).
// ---------------------------------------------------------------------------
__device__ __forceinline__ unsigned f2key(float f) {
    unsigned u = __float_as_uint(f);
    return (u & 0x80000000u) ? ~u : (u | 0x80000000u);
}

__global__ __launch_bounds__(256)
void topk_kernel(float* __restrict__ z)
{
    __shared__ int hist[256];
    __shared__ int s_digit, s_above, s_cnt, s_eq;

    const int row = blockIdx.x;
    const int tid = threadIdx.x;
    const float* __restrict__ h = g_H + (size_t)row * D_LAT;

    if (tid == 0) { s_cnt = 0; s_eq = 0; }

    unsigned prefix = 0, mask = 0;
    int remaining = K_TOP;
    #pragma unroll
    for (int pass = 0; pass < 4; pass++) {
        const int shift = 24 - 8 * pass;
        hist[tid] = 0;
        __syncthreads();
        for (int i = tid; i < D_LAT; i += 256) {
            unsigned key = f2key(h[i]);
            if ((key & mask) == prefix)
                atomicAdd(&hist[(key >> shift) & 255], 1);
        }
        __syncthreads();
        if (tid == 0) {
            int cum = 0;
            int d = 255;
            for (; d >= 0; d--) {
                if (cum + hist[d] >= remaining) break;
                cum += hist[d];
            }
            s_digit = d;
            s_above = cum;
        }
        __syncthreads();
        remaining -= s_above;
        prefix |= ((unsigned)s_digit) << shift;
        mask   |= 0xFFu << shift;
        __syncthreads();
    }

    // select: all keys > prefix, plus `remaining` keys == prefix
    for (int i = tid; i < D_LAT; i += 256) {
        float v = h[i];
        unsigned key = f2key(v);
        bool sel = false;
        if (key > prefix) sel = true;
        else if (key == prefix) {
            if (atomicAdd(&s_eq, 1) < remaining) sel = true;
        }
        if (sel) {
            int p = atomicAdd(&s_cnt, 1);
            z[(size_t)row * D_LAT + i] = v;
            g_topv[row * K_TOP + p] = v;
            g_topi[row * K_TOP + p] = i;
        }
    }
}

// ---------------------------------------------------------------------------
// Kernel 3: recon[row,:] = b_dec + sum_j z[row,j] * W_dec[j,:] over the 64
// active latents. Rank-sort indices so summation order is deterministic
// (independent of atomic completion order in kernel 2).
// ---------------------------------------------------------------------------
__global__ __launch_bounds__(192)
void decode_kernel(const float* __restrict__ Wdec, const float* __restrict__ bdec,
                   float* __restrict__ recon)
{
    __shared__ float sv[K_TOP], sv2[K_TOP];
    __shared__ int   si[K_TOP], si2[K_TOP];
    const int row = blockIdx.x;
    const int tid = threadIdx.x;

    if (tid < K_TOP) {
        sv[tid]  = g_topv[row * K_TOP + tid];
        si[tid]  = g_topi[row * K_TOP + tid];
        sv2[tid] = 0.f;     // defensive init: never read garbage
        si2[tid] = 0;
    }
    __syncthreads();
    if (tid < K_TOP) {
        const int my = si[tid];
        int r = 0;
        #pragma unroll 8
        for (int j = 0; j < K_TOP; j++) r += (si[j] < my);
        si2[r] = my;
        sv2[r] = sv[tid];
    }
    __syncthreads();

    const float4* W4 = reinterpret_cast<const float4*>(Wdec);
    float4 acc = reinterpret_cast<const float4*>(bdec)[tid];
    #pragma unroll 4
    for (int j = 0; j < K_TOP; j++) {
        float4 w = W4[(size_t)si2[j] * (D_IN / 4) + tid];
        float v  = sv2[j];
        acc.x = fmaf(v, w.x, acc.x);
        acc.y = fmaf(v, w.y, acc.y);
        acc.z = fmaf(v, w.z, acc.z);
        acc.w = fmaf(v, w.w, acc.w);
    }
    reinterpret_cast<float4*>(recon)[(size_t)row * (D_IN / 4) + tid] = acc;
}

// ---------------------------------------------------------------------------
extern "C" void kernel_launch(void* const* d_in, const int* in_sizes, int n_in,
                              void* d_out, int out_size)
{
    const float* x     = (const float*)d_in[0];
    const float* W_enc = (const float*)d_in[1];
    const float* b_enc = (const float*)d_in[2];
    const float* W_dec = (const float*)d_in[3];
    const float* b_dec = (const float*)d_in[4];
    // d_in[5] = k_top (known 64, compile-time)

    float* out   = (float*)d_out;
    float* recon = out;                              // [B_ROWS, D_IN]
    float* z     = out + (size_t)B_ROWS * D_IN;      // [B_ROWS, D_LAT]

    cudaMemsetAsync(z, 0, (size_t)B_ROWS * D_LAT * sizeof(float));

    gemm_enc_kernel<<<dim3(D_LAT / BN, B_ROWS / BM), 256>>>(x, W_enc, b_enc);
    topk_kernel<<<B_ROWS, 256>>>(z);
    decode_kernel<<<B_ROWS, 192>>>(W_dec, b_dec, recon);
}

// round 4
// speedup vs baseline: 2.6412x; 2.6412x over previous
#include <cuda_runtime.h>
#include <cuda_bf16.h>
#include <cstdint>

#define B_ROWS 8192
#define D_IN   768
#define D_LAT  12288
#define K_TOP  64
#define K_CAND 96

// ---------------- device scratch (no runtime allocation allowed) -----------
__device__ __nv_bfloat16 g_Xbf[(size_t)B_ROWS * D_IN];
__device__ __nv_bfloat16 g_WbfT[(size_t)D_LAT * D_IN];
__device__ float         g_WT[(size_t)D_LAT * D_IN];
__device__ float         g_H[(size_t)B_ROWS * D_LAT];
__device__ int           g_candi[(size_t)B_ROWS * K_CAND];
__device__ float         g_topv[B_ROWS * K_TOP];
__device__ int           g_topi[B_ROWS * K_TOP];

// ---------------- PTX helpers (compute_103-safe: no tcgen05) ---------------
__device__ __forceinline__ uint32_t smem_u32(const void* p) {
    uint32_t a;
    asm("{ .reg .u64 t; cvta.to.shared.u64 t, %1; cvt.u32.u64 %0, t; }" : "=r"(a) : "l"(p));
    return a;
}
#define CP_ASYNC16(dst, src) \
    asm volatile("cp.async.cg.shared.global [%0], [%1], 16;" :: "r"(dst), "l"(src))
#define CP_COMMIT() asm volatile("cp.async.commit_group;" ::: "memory")
#define CP_WAIT0()  asm volatile("cp.async.wait_group 0;" ::: "memory")

#define LDSM_X4(r0, r1, r2, r3, a) \
    asm volatile("ldmatrix.sync.aligned.m8n8.x4.shared.b16 {%0,%1,%2,%3}, [%4];" \
                 : "=r"(r0), "=r"(r1), "=r"(r2), "=r"(r3) : "r"(a))
#define LDSM_X2(r0, r1, a) \
    asm volatile("ldmatrix.sync.aligned.m8n8.x2.shared.b16 {%0,%1}, [%2];" \
                 : "=r"(r0), "=r"(r1) : "r"(a))

__device__ __forceinline__ void mma16816(float* c, const uint32_t* a, const uint32_t* b) {
    asm volatile(
        "mma.sync.aligned.m16n8k16.row.col.f32.bf16.bf16.f32 "
        "{%0,%1,%2,%3}, {%4,%5,%6,%7}, {%8,%9}, {%0,%1,%2,%3};"
        : "+f"(c[0]), "+f"(c[1]), "+f"(c[2]), "+f"(c[3])
        : "r"(a[0]), "r"(a[1]), "r"(a[2]), "r"(a[3]), "r"(b[0]), "r"(b[1]));
}

// ---------------------------------------------------------------------------
// Prep kernels: X -> bf16 ; W_enc -> transposed fp32 + bf16
// ---------------------------------------------------------------------------
__global__ void convert_x_kernel(const float* __restrict__ X) {
    const size_t n = (size_t)B_ROWS * D_IN / 2;
    const float2* X2 = reinterpret_cast<const float2*>(X);
    __nv_bfloat162* Y = reinterpret_cast<__nv_bfloat162*>(g_Xbf);
    for (size_t i = (size_t)blockIdx.x * blockDim.x + threadIdx.x; i < n;
         i += (size_t)gridDim.x * blockDim.x)
        Y[i] = __float22bfloat162_rn(X2[i]);
}

__global__ void transpose_w_kernel(const float* __restrict__ W) {
    __shared__ float t[32][33];
    const int bx = blockIdx.x;  // over D_LAT/32
    const int by = blockIdx.y;  // over D_IN/32
    const int tx = threadIdx.x, ty = threadIdx.y;
    #pragma unroll
    for (int i = ty; i < 32; i += 8)
        t[i][tx] = W[(size_t)(by * 32 + i) * D_LAT + bx * 32 + tx];
    __syncthreads();
    #pragma unroll
    for (int i = ty; i < 32; i += 8) {
        float v = t[tx][i];
        size_t o = (size_t)(bx * 32 + i) * D_IN + by * 32 + tx;
        g_WT[o]   = v;
        g_WbfT[o] = __float2bfloat16(v);
    }
}

// ---------------------------------------------------------------------------
// Kernel: H ~= X @ W_enc + b_enc  via bf16 mma.sync (approx, for candidates)
// 128x128 block tile, 8 warps (64x32 warp tile), BK=32, cp.async dbl-buffer.
// Smem rows padded to 80B -> ldmatrix conflict-free (r*20 mod 32 all distinct)
// ---------------------------------------------------------------------------
#define BKC    32
#define NCH    (D_IN / BKC)          // 24
#define ROWB   80                    // padded row bytes (32 bf16 = 64B + 16B pad)
#define TILEB  (128 * ROWB)          // 10240 B per operand tile

__global__ __launch_bounds__(256, 1)
void gemm_enc_bf16(const float* __restrict__ bias)
{
    __shared__ __align__(16) char sraw[4 * TILEB];   // A0 A1 B0 B1 = 40960 B

    const uint32_t sbase = smem_u32(sraw);
    const int tid    = threadIdx.x;
    const int wid    = tid >> 5;
    const int lane   = tid & 31;
    const int warp_m = wid >> 2;          // 0..1
    const int warp_n = wid & 3;           // 0..3
    const int row0   = blockIdx.y * 128;
    const int col0   = blockIdx.x * 128;

    const char* Agl = reinterpret_cast<const char*>(g_Xbf);
    const char* Bgl = reinterpret_cast<const char*>(g_WbfT);

    // per-thread load slots: 2 A units + 2 B units per chunk (16B each)
    auto load_chunk = [&](int kc, int buf) {
        #pragma unroll
        for (int t = 0; t < 2; t++) {
            int u   = tid + t * 256;       // 0..511
            int r   = u >> 2;
            int c16 = u & 3;
            uint32_t da = sbase + buf * TILEB + r * ROWB + c16 * 16;
            const char* sa = Agl + ((size_t)(row0 + r) * D_IN + kc * BKC) * 2 + c16 * 16;
            CP_ASYNC16(da, sa);
            uint32_t db = sbase + (2 + buf) * TILEB + r * ROWB + c16 * 16;
            const char* sb = Bgl + ((size_t)(col0 + r) * D_IN + kc * BKC) * 2 + c16 * 16;
            CP_ASYNC16(db, sb);
        }
    };

    float acc[4][4][4];
    #pragma unroll
    for (int i = 0; i < 4; i++)
        #pragma unroll
        for (int j = 0; j < 4; j++)
            #pragma unroll
            for (int q = 0; q < 4; q++) acc[i][j][q] = 0.f;

    // ldmatrix per-lane address components
    const int a_row = warp_m * 64 + (lane & 15);   // + mi*16
    const int a_col = (lane >> 4) * 8;             // + ks*16  (bf16 units)
    const int b_row = warp_n * 32 + (lane & 7);    // + nj*8
    const int b_col = ((lane >> 3) & 1) * 8;       // + ks*16

    load_chunk(0, 0);
    CP_COMMIT();
    CP_WAIT0();
    __syncthreads();

    for (int c = 0; c < NCH; c++) {
        const int buf = c & 1;
        if (c + 1 < NCH) {
            load_chunk(c + 1, buf ^ 1);
            CP_COMMIT();
        }

        const uint32_t sa = sbase + buf * TILEB;
        const uint32_t sb = sbase + (2 + buf) * TILEB;
        #pragma unroll
        for (int ks = 0; ks < 2; ks++) {
            uint32_t af[4][4], bf[4][2];
            #pragma unroll
            for (int mi = 0; mi < 4; mi++) {
                uint32_t addr = sa + (a_row + mi * 16) * ROWB + (a_col + ks * 16) * 2;
                LDSM_X4(af[mi][0], af[mi][1], af[mi][2], af[mi][3], addr);
            }
            #pragma unroll
            for (int nj = 0; nj < 4; nj++) {
                uint32_t addr = sb + (b_row + nj * 8) * ROWB + (b_col + ks * 16) * 2;
                LDSM_X2(bf[nj][0], bf[nj][1], addr);
            }
            #pragma unroll
            for (int mi = 0; mi < 4; mi++)
                #pragma unroll
                for (int nj = 0; nj < 4; nj++)
                    mma16816(acc[mi][nj], af[mi], bf[nj]);
        }

        if (c + 1 < NCH) {
            CP_WAIT0();
            __syncthreads();
        }
    }

    // epilogue: add bias, store fp32 H
    const int er = lane >> 2;          // 0..7
    const int ec = (lane & 3) * 2;     // 0,2,4,6
    #pragma unroll
    for (int mi = 0; mi < 4; mi++) {
        #pragma unroll
        for (int nj = 0; nj < 4; nj++) {
            const int r = row0 + warp_m * 64 + mi * 16 + er;
            const int cc = col0 + warp_n * 32 + nj * 8 + ec;
            const float bx = bias[cc], by = bias[cc + 1];
            float2 v0 = make_float2(acc[mi][nj][0] + bx, acc[mi][nj][1] + by);
            float2 v1 = make_float2(acc[mi][nj][2] + bx, acc[mi][nj][3] + by);
            *reinterpret_cast<float2*>(g_H + (size_t)r * D_LAT + cc) = v0;
            *reinterpret_cast<float2*>(g_H + (size_t)(r + 8) * D_LAT + cc) = v1;
        }
    }
}

// ---------------------------------------------------------------------------
// Kernel: per-row top-96 CANDIDATE indices via 4-pass radix select on approx H
// ---------------------------------------------------------------------------
__device__ __forceinline__ unsigned f2key(float f) {
    unsigned u = __float_as_uint(f);
    return (u & 0x80000000u) ? ~u : (u | 0x80000000u);
}

__global__ __launch_bounds__(256)
void topk_kernel()
{
    __shared__ int hist[256];
    __shared__ int s_digit, s_above, s_cnt, s_eq;

    const int row = blockIdx.x;
    const int tid = threadIdx.x;
    const float* __restrict__ h = g_H + (size_t)row * D_LAT;

    if (tid == 0) { s_cnt = 0; s_eq = 0; }

    unsigned prefix = 0, mask = 0;
    int remaining = K_CAND;
    #pragma unroll
    for (int pass = 0; pass < 4; pass++) {
        const int shift = 24 - 8 * pass;
        hist[tid] = 0;
        __syncthreads();
        for (int i = tid; i < D_LAT; i += 256) {
            unsigned key = f2key(h[i]);
            if ((key & mask) == prefix)
                atomicAdd(&hist[(key >> shift) & 255], 1);
        }
        __syncthreads();
        if (tid == 0) {
            int cum = 0;
            int d = 255;
            for (; d >= 0; d--) {
                if (cum + hist[d] >= remaining) break;
                cum += hist[d];
            }
            s_digit = d;
            s_above = cum;
        }
        __syncthreads();
        remaining -= s_above;
        prefix |= ((unsigned)s_digit) << shift;
        mask   |= 0xFFu << shift;
        __syncthreads();
    }

    for (int i = tid; i < D_LAT; i += 256) {
        unsigned key = f2key(h[i]);
        bool sel = false;
        if (key > prefix) sel = true;
        else if (key == prefix) {
            if (atomicAdd(&s_eq, 1) < remaining) sel = true;
        }
        if (sel) {
            int p = atomicAdd(&s_cnt, 1);
            g_candi[(size_t)row * K_CAND + p] = i;
        }
    }
}

// ---------------------------------------------------------------------------
// Kernel: exact fp32 recompute of the 96 candidates, exact top-64 selection
// (jax tie semantics: value desc, index asc), writes z + compact lists.
// ---------------------------------------------------------------------------
__global__ __launch_bounds__(256)
void recompute_kernel(const float* __restrict__ X, const float* __restrict__ bias,
                      float* __restrict__ z)
{
    __shared__ float xs[D_IN];
    __shared__ int   ci[K_CAND];
    __shared__ float cv[K_CAND];

    const int row = blockIdx.x;
    const int tid = threadIdx.x;
    for (int i = tid; i < D_IN; i += 256)
        xs[i] = X[(size_t)row * D_IN + i];
    if (tid < K_CAND)
        ci[tid] = g_candi[(size_t)row * K_CAND + tid];
    __syncthreads();

    const int wid = tid >> 5, lane = tid & 31;
    for (int c = wid; c < K_CAND; c += 8) {
        const float* wr = g_WT + (size_t)ci[c] * D_IN;
        float s = 0.f;
        #pragma unroll 4
        for (int k = lane; k < D_IN; k += 32)
            s = fmaf(xs[k], wr[k], s);
        #pragma unroll
        for (int o = 16; o; o >>= 1)
            s += __shfl_xor_sync(0xffffffff, s, o);
        if (lane == 0) cv[c] = s + bias[ci[c]];
    }
    __syncthreads();

    if (tid < K_CAND) {
        const float v  = cv[tid];
        const int   id = ci[tid];
        int r = 0;
        #pragma unroll 8
        for (int j = 0; j < K_CAND; j++) {
            float vj = cv[j];
            r += (vj > v) || (vj == v && ci[j] < id);
        }
        if (r < K_TOP) {
            z[(size_t)row * D_LAT + id] = v;
            g_topv[row * K_TOP + r] = v;
            g_topi[row * K_TOP + r] = id;
        }
    }
}

// ---------------------------------------------------------------------------
// Kernel: sparse decode recon = b_dec + sum_j z_j * W_dec[j,:]
// ---------------------------------------------------------------------------
__global__ __launch_bounds__(192)
void decode_kernel(const float* __restrict__ Wdec, const float* __restrict__ bdec,
                   float* __restrict__ recon)
{
    __shared__ float sv[K_TOP], sv2[K_TOP];
    __shared__ int   si[K_TOP], si2[K_TOP];
    const int row = blockIdx.x;
    const int tid = threadIdx.x;

    if (tid < K_TOP) {
        sv[tid]  = g_topv[row * K_TOP + tid];
        si[tid]  = g_topi[row * K_TOP + tid];
        sv2[tid] = 0.f;
        si2[tid] = 0;
    }
    __syncthreads();
    if (tid < K_TOP) {
        const int my = si[tid];
        int r = 0;
        #pragma unroll 8
        for (int j = 0; j < K_TOP; j++) r += (si[j] < my);
        si2[r] = my;
        sv2[r] = sv[tid];
    }
    __syncthreads();

    const float4* W4 = reinterpret_cast<const float4*>(Wdec);
    float4 acc = reinterpret_cast<const float4*>(bdec)[tid];
    #pragma unroll 4
    for (int j = 0; j < K_TOP; j++) {
        float4 w = W4[(size_t)si2[j] * (D_IN / 4) + tid];
        float v  = sv2[j];
        acc.x = fmaf(v, w.x, acc.x);
        acc.y = fmaf(v, w.y, acc.y);
        acc.z = fmaf(v, w.z, acc.z);
        acc.w = fmaf(v, w.w, acc.w);
    }
    reinterpret_cast<float4*>(recon)[(size_t)row * (D_IN / 4) + tid] = acc;
}

// ---------------------------------------------------------------------------
extern "C" void kernel_launch(void* const* d_in, const int* in_sizes, int n_in,
                              void* d_out, int out_size)
{
    const float* x     = (const float*)d_in[0];
    const float* W_enc = (const float*)d_in[1];
    const float* b_enc = (const float*)d_in[2];
    const float* W_dec = (const float*)d_in[3];
    const float* b_dec = (const float*)d_in[4];

    float* out   = (float*)d_out;
    float* recon = out;                              // [B_ROWS, D_IN]
    float* z     = out + (size_t)B_ROWS * D_IN;      // [B_ROWS, D_LAT]

    cudaMemsetAsync(z, 0, (size_t)B_ROWS * D_LAT * sizeof(float));

    convert_x_kernel<<<2048, 256>>>(x);
    transpose_w_kernel<<<dim3(D_LAT / 32, D_IN / 32), dim3(32, 8)>>>(W_enc);

    gemm_enc_bf16<<<dim3(D_LAT / 128, B_ROWS / 128), 256>>>(b_enc);

    topk_kernel<<<B_ROWS, 256>>>();
    recompute_kernel<<<B_ROWS, 256>>>(x, b_enc, z);
    decode_kernel<<<B_ROWS, 192>>>(W_dec, b_dec, recon);
}

// round 5
// speedup vs baseline: 2.9194x; 1.1053x over previous
#include <cuda_runtime.h>
#include <cuda_bf16.h>
#include <cstdint>

#define B_ROWS 8192
#define D_IN   768
#define D_LAT  12288
#define K_TOP  64
#define K_CAND 96

// ---------------- device scratch (no runtime allocation allowed) -----------
__device__ __nv_bfloat16 g_Xbf[(size_t)B_ROWS * D_IN];
__device__ __nv_bfloat16 g_WbfT[(size_t)D_LAT * D_IN];
__device__ float         g_WT[(size_t)D_LAT * D_IN];
__device__ uint16_t      g_Hk[(size_t)B_ROWS * D_LAT];   // 16-bit ordered keys of approx H
__device__ int           g_candi[(size_t)B_ROWS * K_CAND];

// ---------------- PTX helpers (compute_103-safe: no tcgen05) ---------------
__device__ __forceinline__ uint32_t smem_u32(const void* p) {
    uint32_t a;
    asm("{ .reg .u64 t; cvta.to.shared.u64 t, %1; cvt.u32.u64 %0, t; }" : "=r"(a) : "l"(p));
    return a;
}
#define CP_ASYNC16(dst, src) \
    asm volatile("cp.async.cg.shared.global [%0], [%1], 16;" :: "r"(dst), "l"(src))
#define CP_COMMIT() asm volatile("cp.async.commit_group;" ::: "memory")
#define CP_WAIT0()  asm volatile("cp.async.wait_group 0;" ::: "memory")

#define LDSM_X4(r0, r1, r2, r3, a) \
    asm volatile("ldmatrix.sync.aligned.m8n8.x4.shared.b16 {%0,%1,%2,%3}, [%4];" \
                 : "=r"(r0), "=r"(r1), "=r"(r2), "=r"(r3) : "r"(a))
#define LDSM_X2(r0, r1, a) \
    asm volatile("ldmatrix.sync.aligned.m8n8.x2.shared.b16 {%0,%1}, [%2];" \
                 : "=r"(r0), "=r"(r1) : "r"(a))

__device__ __forceinline__ void mma16816(float* c, const uint32_t* a, const uint32_t* b) {
    asm volatile(
        "mma.sync.aligned.m16n8k16.row.col.f32.bf16.bf16.f32 "
        "{%0,%1,%2,%3}, {%4,%5,%6,%7}, {%8,%9}, {%0,%1,%2,%3};"
        : "+f"(c[0]), "+f"(c[1]), "+f"(c[2]), "+f"(c[3])
        : "r"(a[0]), "r"(a[1]), "r"(a[2]), "r"(a[3]), "r"(b[0]), "r"(b[1]));
}

// monotonic bf16 -> u16 key (bigger float => bigger key)
__device__ __forceinline__ uint16_t f2key16(float v) {
    uint16_t u = __bfloat16_as_ushort(__float2bfloat16(v));
    return (u & 0x8000) ? (uint16_t)~u : (uint16_t)(u | 0x8000);
}

// ---------------------------------------------------------------------------
// Prep kernels: X -> bf16 ; W_enc -> transposed fp32 + bf16
// ---------------------------------------------------------------------------
__global__ void convert_x_kernel(const float* __restrict__ X) {
    const size_t n = (size_t)B_ROWS * D_IN / 2;
    const float2* X2 = reinterpret_cast<const float2*>(X);
    __nv_bfloat162* Y = reinterpret_cast<__nv_bfloat162*>(g_Xbf);
    for (size_t i = (size_t)blockIdx.x * blockDim.x + threadIdx.x; i < n;
         i += (size_t)gridDim.x * blockDim.x)
        Y[i] = __float22bfloat162_rn(X2[i]);
}

__global__ void transpose_w_kernel(const float* __restrict__ W) {
    __shared__ float t[32][33];
    const int bx = blockIdx.x;  // over D_LAT/32
    const int by = blockIdx.y;  // over D_IN/32
    const int tx = threadIdx.x, ty = threadIdx.y;
    #pragma unroll
    for (int i = ty; i < 32; i += 8)
        t[i][tx] = W[(size_t)(by * 32 + i) * D_LAT + bx * 32 + tx];
    __syncthreads();
    #pragma unroll
    for (int i = ty; i < 32; i += 8) {
        float v = t[tx][i];
        size_t o = (size_t)(bx * 32 + i) * D_IN + by * 32 + tx;
        g_WT[o]   = v;
        g_WbfT[o] = __float2bfloat16(v);
    }
}

// ---------------------------------------------------------------------------
// Kernel: H ~= X @ W_enc + b_enc  via bf16 mma.sync; epilogue stores u16 keys.
// 128x128 block tile, 8 warps (64x32 warp tile), BK=32, cp.async dbl-buffer.
// ---------------------------------------------------------------------------
#define BKC    32
#define NCH    (D_IN / BKC)          // 24
#define ROWB   80                    // padded row bytes (conflict-free ldmatrix)
#define TILEB  (128 * ROWB)          // 10240 B per operand tile

__global__ __launch_bounds__(256, 2)
void gemm_enc_bf16(const float* __restrict__ bias)
{
    __shared__ __align__(16) char sraw[4 * TILEB];   // A0 A1 B0 B1 = 40960 B

    const uint32_t sbase = smem_u32(sraw);
    const int tid    = threadIdx.x;
    const int wid    = tid >> 5;
    const int lane   = tid & 31;
    const int warp_m = wid >> 2;          // 0..1
    const int warp_n = wid & 3;           // 0..3
    const int row0   = blockIdx.y * 128;
    const int col0   = blockIdx.x * 128;

    const char* Agl = reinterpret_cast<const char*>(g_Xbf);
    const char* Bgl = reinterpret_cast<const char*>(g_WbfT);

    auto load_chunk = [&](int kc, int buf) {
        #pragma unroll
        for (int t = 0; t < 2; t++) {
            int u   = tid + t * 256;       // 0..511
            int r   = u >> 2;
            int c16 = u & 3;
            uint32_t da = sbase + buf * TILEB + r * ROWB + c16 * 16;
            const char* sa = Agl + ((size_t)(row0 + r) * D_IN + kc * BKC) * 2 + c16 * 16;
            CP_ASYNC16(da, sa);
            uint32_t db = sbase + (2 + buf) * TILEB + r * ROWB + c16 * 16;
            const char* sb = Bgl + ((size_t)(col0 + r) * D_IN + kc * BKC) * 2 + c16 * 16;
            CP_ASYNC16(db, sb);
        }
    };

    float acc[4][4][4];
    #pragma unroll
    for (int i = 0; i < 4; i++)
        #pragma unroll
        for (int j = 0; j < 4; j++)
            #pragma unroll
            for (int q = 0; q < 4; q++) acc[i][j][q] = 0.f;

    const int a_row = warp_m * 64 + (lane & 15);
    const int a_col = (lane >> 4) * 8;
    const int b_row = warp_n * 32 + (lane & 7);
    const int b_col = ((lane >> 3) & 1) * 8;

    load_chunk(0, 0);
    CP_COMMIT();
    CP_WAIT0();
    __syncthreads();

    for (int c = 0; c < NCH; c++) {
        const int buf = c & 1;
        if (c + 1 < NCH) {
            load_chunk(c + 1, buf ^ 1);
            CP_COMMIT();
        }

        const uint32_t sa = sbase + buf * TILEB;
        const uint32_t sb = sbase + (2 + buf) * TILEB;
        #pragma unroll
        for (int ks = 0; ks < 2; ks++) {
            uint32_t af[4][4], bf[4][2];
            #pragma unroll
            for (int mi = 0; mi < 4; mi++) {
                uint32_t addr = sa + (a_row + mi * 16) * ROWB + (a_col + ks * 16) * 2;
                LDSM_X4(af[mi][0], af[mi][1], af[mi][2], af[mi][3], addr);
            }
            #pragma unroll
            for (int nj = 0; nj < 4; nj++) {
                uint32_t addr = sb + (b_row + nj * 8) * ROWB + (b_col + ks * 16) * 2;
                LDSM_X2(bf[nj][0], bf[nj][1], addr);
            }
            #pragma unroll
            for (int mi = 0; mi < 4; mi++)
                #pragma unroll
                for (int nj = 0; nj < 4; nj++)
                    mma16816(acc[mi][nj], af[mi], bf[nj]);
        }

        if (c + 1 < NCH) {
            CP_WAIT0();
            __syncthreads();
        }
    }

    // epilogue: add bias, quantize to ordered u16 keys, store packed pairs
    const int er = lane >> 2;          // 0..7
    const int ec = (lane & 3) * 2;     // 0,2,4,6
    #pragma unroll
    for (int mi = 0; mi < 4; mi++) {
        #pragma unroll
        for (int nj = 0; nj < 4; nj++) {
            const int r  = row0 + warp_m * 64 + mi * 16 + er;
            const int cc = col0 + warp_n * 32 + nj * 8 + ec;
            const float bx = bias[cc], by = bias[cc + 1];
            uint32_t p0 = (uint32_t)f2key16(acc[mi][nj][0] + bx) |
                          ((uint32_t)f2key16(acc[mi][nj][1] + by) << 16);
            uint32_t p1 = (uint32_t)f2key16(acc[mi][nj][2] + bx) |
                          ((uint32_t)f2key16(acc[mi][nj][3] + by) << 16);
            *reinterpret_cast<uint32_t*>(g_Hk + (size_t)r * D_LAT + cc) = p0;
            *reinterpret_cast<uint32_t*>(g_Hk + (size_t)(r + 8) * D_LAT + cc) = p1;
        }
    }
}

// ---------------------------------------------------------------------------
// Kernel: per-row top-96 candidate indices from u16 keys.
// Row cached in smem; 2 histogram passes (hi byte, lo byte) with
// warp-aggregated atomics; final select pass.
// ---------------------------------------------------------------------------
__device__ __forceinline__ void hadd(int* hist, int bucket) {
    unsigned m = __match_any_sync(0xffffffffu, bucket);
    if ((threadIdx.x & 31) == __ffs(m) - 1)
        atomicAdd(&hist[bucket], __popc(m));
}

__global__ __launch_bounds__(256)
void topk_kernel()
{
    __shared__ uint32_t skeys[D_LAT / 2];   // 24 KB
    __shared__ int hist[257];
    __shared__ int s_d1, s_rem1, s_thresh, s_rem2, s_cnt, s_eq;

    const int row = blockIdx.x;
    const int tid = threadIdx.x;

    const uint4* src = reinterpret_cast<const uint4*>(g_Hk + (size_t)row * D_LAT);
    uint4* dst = reinterpret_cast<uint4*>(skeys);
    #pragma unroll
    for (int i = tid; i < D_LAT / 8; i += 256) dst[i] = src[i];
    hist[tid] = 0;
    if (tid == 0) { hist[256] = 0; s_cnt = 0; s_eq = 0; }
    __syncthreads();

    // pass 1: histogram of high byte
    #pragma unroll 4
    for (int i = tid; i < D_LAT / 2; i += 256) {
        uint32_t w = skeys[i];
        hadd(hist, (int)((w >> 8) & 0xFF));
        hadd(hist, (int)(w >> 24));
    }
    __syncthreads();
    if (tid == 0) {
        int cum = 0, d = 255;
        for (; d > 0; d--) {
            if (cum + hist[d] >= K_CAND) break;
            cum += hist[d];
        }
        s_d1 = d;
        s_rem1 = K_CAND - cum;
    }
    __syncthreads();
    const int d1 = s_d1, rem1 = s_rem1;
    hist[tid] = 0;
    if (tid == 0) hist[256] = 0;
    __syncthreads();

    // pass 2: histogram of low byte among keys with high byte == d1
    #pragma unroll 4
    for (int i = tid; i < D_LAT / 2; i += 256) {
        uint32_t w = skeys[i];
        int k0 = (int)(w & 0xFFFF), k1 = (int)(w >> 16);
        hadd(hist, (k0 >> 8) == d1 ? (k0 & 0xFF) : 256);
        hadd(hist, (k1 >> 8) == d1 ? (k1 & 0xFF) : 256);
    }
    __syncthreads();
    if (tid == 0) {
        int cum = 0, e = 255;
        for (; e > 0; e--) {
            if (cum + hist[e] >= rem1) break;
            cum += hist[e];
        }
        s_thresh = (d1 << 8) | e;
        s_rem2 = rem1 - cum;
    }
    __syncthreads();
    const int thresh = s_thresh, rem2 = s_rem2;

    // select: keys > thresh, plus rem2 ties at == thresh
    int* cand = g_candi + (size_t)row * K_CAND;
    for (int i = tid; i < D_LAT / 2; i += 256) {
        uint32_t w = skeys[i];
        int k0 = (int)(w & 0xFFFF), k1 = (int)(w >> 16);
        if (k0 > thresh)       cand[atomicAdd(&s_cnt, 1)] = 2 * i;
        else if (k0 == thresh && atomicAdd(&s_eq, 1) < rem2)
                               cand[atomicAdd(&s_cnt, 1)] = 2 * i;
        if (k1 > thresh)       cand[atomicAdd(&s_cnt, 1)] = 2 * i + 1;
        else if (k1 == thresh && atomicAdd(&s_eq, 1) < rem2)
                               cand[atomicAdd(&s_cnt, 1)] = 2 * i + 1;
    }
}

// ---------------------------------------------------------------------------
// Kernel: fused exact recompute (fp32) of the 96 candidates + exact top-64
// (jax tie semantics: value desc, index asc) + z scatter + sparse decode.
// ---------------------------------------------------------------------------
__global__ __launch_bounds__(256)
void recon_kernel(const float* __restrict__ X, const float* __restrict__ b_enc,
                  const float* __restrict__ Wdec, const float* __restrict__ bdec,
                  float* __restrict__ z, float* __restrict__ recon)
{
    __shared__ __align__(16) float xs[D_IN];
    __shared__ int   ci[K_CAND];
    __shared__ float cv[K_CAND];
    __shared__ float sv[K_TOP];
    __shared__ int   si[K_TOP];

    const int row = blockIdx.x;
    const int tid = threadIdx.x;
    const int wid = tid >> 5, lane = tid & 31;

    {
        const float4* X4 = reinterpret_cast<const float4*>(X + (size_t)row * D_IN);
        float4* xs4 = reinterpret_cast<float4*>(xs);
        if (tid < D_IN / 4) xs4[tid] = X4[tid];
    }
    if (tid < K_CAND)
        ci[tid] = g_candi[(size_t)row * K_CAND + tid];
    __syncthreads();

    // 96 exact dot products, one warp per candidate, float4-vectorized
    const float4* xs4 = reinterpret_cast<const float4*>(xs);
    for (int c = wid; c < K_CAND; c += 8) {
        const float4* wr = reinterpret_cast<const float4*>(g_WT + (size_t)ci[c] * D_IN);
        float s = 0.f;
        #pragma unroll
        for (int j = 0; j < D_IN / 128; j++) {      // 6 float4 per lane
            float4 a = xs4[lane + 32 * j];
            float4 b = wr[lane + 32 * j];
            s = fmaf(a.x, b.x, s); s = fmaf(a.y, b.y, s);
            s = fmaf(a.z, b.z, s); s = fmaf(a.w, b.w, s);
        }
        #pragma unroll
        for (int o = 16; o; o >>= 1) s += __shfl_xor_sync(0xffffffff, s, o);
        if (lane == 0) cv[c] = s + b_enc[ci[c]];
    }
    __syncthreads();

    // exact top-64 among 96 (value desc, index asc on ties)
    if (tid < K_CAND) {
        const float v  = cv[tid];
        const int   id = ci[tid];
        int r = 0;
        #pragma unroll 8
        for (int j = 0; j < K_CAND; j++) {
            float vj = cv[j];
            r += (vj > v) || (vj == v && ci[j] < id);
        }
        if (r < K_TOP) {
            z[(size_t)row * D_LAT + id] = v;
            sv[r] = v;
            si[r] = id;
        }
    }
    __syncthreads();

    // sparse decode: recon[row,:] = b_dec + sum_j sv[j] * W_dec[si[j],:]
    if (tid < D_IN / 4) {
        const float4* W4 = reinterpret_cast<const float4*>(Wdec);
        float4 acc = reinterpret_cast<const float4*>(bdec)[tid];
        #pragma unroll 4
        for (int j = 0; j < K_TOP; j++) {
            float4 w = W4[(size_t)si[j] * (D_IN / 4) + tid];
            float v  = sv[j];
            acc.x = fmaf(v, w.x, acc.x);
            acc.y = fmaf(v, w.y, acc.y);
            acc.z = fmaf(v, w.z, acc.z);
            acc.w = fmaf(v, w.w, acc.w);
        }
        reinterpret_cast<float4*>(recon)[(size_t)row * (D_IN / 4) + tid] = acc;
    }
}

// ---------------------------------------------------------------------------
extern "C" void kernel_launch(void* const* d_in, const int* in_sizes, int n_in,
                              void* d_out, int out_size)
{
    const float* x     = (const float*)d_in[0];
    const float* W_enc = (const float*)d_in[1];
    const float* b_enc = (const float*)d_in[2];
    const float* W_dec = (const float*)d_in[3];
    const float* b_dec = (const float*)d_in[4];

    float* out   = (float*)d_out;
    float* recon = out;                              // [B_ROWS, D_IN]
    float* z     = out + (size_t)B_ROWS * D_IN;      // [B_ROWS, D_LAT]

    cudaMemsetAsync(z, 0, (size_t)B_ROWS * D_LAT * sizeof(float));

    convert_x_kernel<<<2048, 256>>>(x);
    transpose_w_kernel<<<dim3(D_LAT / 32, D_IN / 32), dim3(32, 8)>>>(W_enc);

    gemm_enc_bf16<<<dim3(D_LAT / 128, B_ROWS / 128), 256>>>(b_enc);

    topk_kernel<<<B_ROWS, 256>>>();
    recon_kernel<<<B_ROWS, 256>>>(x, b_enc, W_dec, b_dec, z, recon);
}